// round 8
// baseline (speedup 1.0000x reference)
#include <cuda_runtime.h>
#include <cuda_bf16.h>
#include <math.h>

// Problem dims
#define BB   32
#define LL   1024
#define DD   512
#define HH   512
#define G4   2048
#define FF   256
#define OUTD 100
#define NCTA_LSTM 128
#define WIN  64          // exact softmax window; beyond this exp(score*decay - m) == exp(-m) in fp32

// ---------------- scratch (device globals; no allocation) ----------------
__device__ float g_pre  [BB * LL * G4];     // gates pre-activation, PERMUTED: [b][t][j*4+gate]
__device__ float g_cpart[BB * G4];          // concept part + biases (original gate order)
__device__ float g_hout [BB * LL * HH];     // LSTM hidden states
__device__ float g_hbuf [2 * HH * BB];      // h double buffer [buf][k][b]
__device__ float g_mlp  [BB * LL * DD];     // mlp_out
__device__ float g_P    [BB * LL * HH];     // cumsum of hout over t
__device__ float g_csum [BB * 16 * HH];     // per-chunk sums for blocked scan
__device__ float g_wgt  [BB * LL * HH];     // attention output
__device__ float g_h1   [BB * LL * FF];     // relu(W1 ...)
__device__ unsigned g_flags[NCTA_LSTM * 32]; // per-CTA step flags, 128B apart

// ---------------- f32x2 packed helpers ----------------
__device__ __forceinline__ unsigned long long pk2(float lo, float hi) {
    unsigned long long r;
    asm("mov.b64 %0, {%1, %2};" : "=l"(r) : "f"(lo), "f"(hi));
    return r;
}
__device__ __forceinline__ void upk2(float& lo, float& hi, unsigned long long v) {
    asm("mov.b64 {%0, %1}, %2;" : "=f"(lo), "=f"(hi) : "l"(v));
}
__device__ __forceinline__ void ffma2(unsigned long long& d, unsigned long long a,
                                      unsigned long long b) {
    asm("fma.rn.f32x2 %0, %1, %2, %0;" : "+l"(d) : "l"(a), "l"(b));
}
__device__ __forceinline__ unsigned ld_acq(const unsigned* p) {
    unsigned v;
    asm volatile("ld.acquire.gpu.global.u32 %0, [%1];" : "=r"(v) : "l"(p));
    return v;
}
__device__ __forceinline__ void st_rel(unsigned* p, unsigned v) {
    asm volatile("st.release.gpu.global.u32 [%0], %1;" :: "l"(p), "r"(v));
}

// ---------------- init: zero h buffers + barrier state ----------------
__global__ void k_init() {
    int i = blockIdx.x * 256 + threadIdx.x;
    if (i < 2 * HH * BB) g_hbuf[i] = 0.0f;
    if (i < NCTA_LSTM * 32) g_flags[i] = 0u;
}

// ---------------- cpart[b][g] = emb[concepts[b]] . Wih[g][512:1024] + bih[g] + bhh[g] --------
__global__ void k_cpart(const float* __restrict__ emb, const int* __restrict__ concepts,
                        const float* __restrict__ Wih, const float* __restrict__ bih,
                        const float* __restrict__ bhh) {
    int b = blockIdx.x >> 3;
    int g = ((blockIdx.x & 7) << 8) + threadIdx.x;   // 8 chunks * 256
    const float4* e  = (const float4*)(emb + (long)concepts[b] * HH);
    const float4* w  = (const float4*)(Wih + (long)g * (2 * DD) + DD);
    float acc = bih[g] + bhh[g];
#pragma unroll 4
    for (int k = 0; k < HH / 4; k++) {
        float4 wv = __ldg(w + k);
        float4 ev = __ldg(e + k);
        acc += wv.x * ev.x + wv.y * ev.y + wv.z * ev.z + wv.w * ev.w;
    }
    g_cpart[b * G4 + g] = acc;
}

// ---------------- SGEMM (f32x2): C[M,N] = A[M,K] * W[N,:K]^T (+bias) (+rowvec) ----
// BM=128, BN=128, BK=16, 256 threads, 8x8 tile as 8x4 f32x2 pairs.
// Per k per warp: 4 LDS.128 + 12 packs + 32 FFMA2 -> fma-pipe bound at 2x scalar rate.
// __launch_bounds__(256,2): 2 CTAs/SM for latency hiding.
template<bool RELU, bool PERM>
__global__ void __launch_bounds__(256, 2)
k_gemm(const float* __restrict__ A, int lda,
       const float* __restrict__ W, int ldw,
       const float* __restrict__ bias,
       const float* __restrict__ rowvec,
       float* __restrict__ C, int ldc,
       int N, int K) {
    __shared__ float As[16 * 132];
    __shared__ float Bs[16 * 132];
    int tid = threadIdx.x;
    int bx = blockIdx.x, by = blockIdx.y;
    int tx = tid & 15, ty = tid >> 4;    // tx: n (8 cols), ty: m (8 rows)

    unsigned long long acc2[8][4];
#pragma unroll
    for (int i = 0; i < 8; i++)
#pragma unroll
        for (int j = 0; j < 4; j++) acc2[i][j] = 0ull;

    int row = tid >> 2;              // 0..63
    int kl  = (tid & 3) * 4;         // 0,4,8,12
    const float* Abase = A + (long)(by * 128 + row) * lda + kl;
    int n0l = bx * 128 + row, n1l = n0l + 64;
    const float* W0 = (n0l < N) ? (W + (long)n0l * ldw + kl) : nullptr;
    const float* W1 = (n1l < N) ? (W + (long)n1l * ldw + kl) : nullptr;

    for (int kt = 0; kt < K; kt += 16) {
        float4 a0 = *(const float4*)(Abase + kt);
        float4 a1 = *(const float4*)(Abase + kt + (long)64 * lda);
        float4 b0 = make_float4(0.f, 0.f, 0.f, 0.f);
        float4 b1 = make_float4(0.f, 0.f, 0.f, 0.f);
        if (W0) b0 = *(const float4*)(W0 + kt);
        if (W1) b1 = *(const float4*)(W1 + kt);
#pragma unroll
        for (int q = 0; q < 4; q++) {
            float av0 = q == 0 ? a0.x : q == 1 ? a0.y : q == 2 ? a0.z : a0.w;
            float av1 = q == 0 ? a1.x : q == 1 ? a1.y : q == 2 ? a1.z : a1.w;
            float bv0 = q == 0 ? b0.x : q == 1 ? b0.y : q == 2 ? b0.z : b0.w;
            float bv1 = q == 0 ? b1.x : q == 1 ? b1.y : q == 2 ? b1.z : b1.w;
            As[(kl + q) * 132 + row]      = av0;
            As[(kl + q) * 132 + row + 64] = av1;
            Bs[(kl + q) * 132 + row]      = bv0;
            Bs[(kl + q) * 132 + row + 64] = bv1;
        }
        __syncthreads();
#pragma unroll
        for (int k = 0; k < 16; k++) {
            float4 av0 = *(const float4*)&As[k * 132 + ty * 8];
            float4 av1 = *(const float4*)&As[k * 132 + ty * 8 + 4];
            float4 bv0 = *(const float4*)&Bs[k * 132 + tx * 8];
            float4 bv1 = *(const float4*)&Bs[k * 132 + tx * 8 + 4];
            unsigned long long bp[4];
            bp[0] = pk2(bv0.x, bv0.y);
            bp[1] = pk2(bv0.z, bv0.w);
            bp[2] = pk2(bv1.x, bv1.y);
            bp[3] = pk2(bv1.z, bv1.w);
            float a[8] = {av0.x, av0.y, av0.z, av0.w, av1.x, av1.y, av1.z, av1.w};
#pragma unroll
            for (int i = 0; i < 8; i++) {
                unsigned long long ap = pk2(a[i], a[i]);
                ffma2(acc2[i][0], ap, bp[0]);
                ffma2(acc2[i][1], ap, bp[1]);
                ffma2(acc2[i][2], ap, bp[2]);
                ffma2(acc2[i][3], ap, bp[3]);
            }
        }
        __syncthreads();
    }

    int m0 = by * 128 + ty * 8, nn0 = bx * 128 + tx * 8;
#pragma unroll
    for (int i = 0; i < 8; i++) {
        int m = m0 + i;
        const float* rv = rowvec ? (rowvec + (long)(m >> 10) * N) : nullptr;
        float accf[8];
#pragma unroll
        for (int jp = 0; jp < 4; jp++) upk2(accf[jp * 2], accf[jp * 2 + 1], acc2[i][jp]);
#pragma unroll
        for (int j = 0; j < 8; j++) {
            int n = nn0 + j;
            if (n < N) {
                float v = accf[j];
                if (bias) v += bias[n];
                if (rv)   v += rv[n];
                if (RELU) v = fmaxf(v, 0.0f);
                int np = PERM ? (((n & 511) << 2) | (n >> 9)) : n;
                C[(long)m * ldc + np] = v;
            }
        }
    }
}

// ---------------- persistent LSTM (per-warp producer polling, fused reduce+act) --------
// 128 CTAs x 256 threads. CTA owns hidden dims j0..j0+3 => 16 gate rows.
// Warp w consumes h rows [64w, 64w+64) = output of CTAs 16w..16w+15 only:
// each warp polls its 16 producer flags, stages its own 8KB, computes -- no
// CTA-wide sync until the partial reduction. Two __syncthreads per step.
// Partials swizzled in smem so 128 act-threads read 4 gates x 16 k-partials directly.
__global__ void __launch_bounds__(256, 1)
k_lstm(const float* __restrict__ pre, const float* __restrict__ Whh) {
    extern __shared__ float sm[];
    float* w_t = sm;                   // [512][16]  k-major weights
    float* h_s = w_t + 512 * 16;       // [512][32]  staged h
    float* ps  = h_s + 512 * 32;       // [16][512]  swizzled k-split partials
    float* c_s = ps + 16 * 512;        // [128]      cell state

    int tid  = threadIdx.x;
    int j0   = blockIdx.x * 4;
    int w    = tid >> 5;
    int lane = tid & 31;

    // load Whh slice transposed: w_t[k*16 + lr] = Whh[grow(lr)][k]
    for (int i = tid; i < 16 * 512; i += 256) {
        int lr = i & 15, k = i >> 4;
        int grow = ((lr >> 2) << 9) + j0 + (lr & 3);
        w_t[k * 16 + lr] = Whh[(long)grow * HH + k];
    }
    if (tid < 128) c_s[tid] = 0.0f;

    // compute-role indices
    int ks  = tid >> 4;           // k-slice 0..15 (width 32); warp w owns ks in {2w, 2w+1}
    int l16 = tid & 15;
    int rt  = l16 >> 3;           // row half
    int bt  = l16 & 7;            // batch group of 4
    int rowid = rt * 8 + bt;
    int xlow  = ((rowid >> 2) & 1) << 2;
    const float* wbase = w_t + (ks * 32) * 16 + rt * 8;
    const float* hbase = h_s + (ks * 32) * 32 + bt * 4;
    float* psbase = ps + ks * 512 + rowid * 32;

    // activation-role (tid < 128): hidden jl = tid>>5, batch ab = tid&31
    int jl = tid >> 5, ab = tid & 31;
    long preoff = (long)ab * LL * G4 + (j0 + jl) * 4;    // permuted pre: float4 of 4 gates
    int low_r = (((ab & 3) << 1) | (jl & 1)) ^ (((ab >> 4) & 1) << 2);
    int gbase[4];
#pragma unroll
    for (int g = 0; g < 4; g++) {
        int rp   = (g * 2 + (jl >> 1)) & 3;
        int slot = rp ^ ((ab >> 2) & 3);
        gbase[g] = (g >> 1) * 256 + (ab >> 2) * 32 + slot * 8 + low_r;
    }

    unsigned* myflag = &g_flags[blockIdx.x * 32];
    const unsigned* pollflag = &g_flags[(w * 16 + (lane & 15)) * 32];

    __syncthreads();

    float4 pf4 = make_float4(0.f, 0.f, 0.f, 0.f);
    if (tid < 128) pf4 = *(const float4*)(pre + preoff);    // t = 0

    for (int t = 0; t < LL; t++) {
        // ---- per-warp: wait for this warp's 16 producers, stage own h rows ----
        while (ld_acq(pollflag) < (unsigned)t) { }
        __syncwarp();
        {
            const float4* hin  = (const float4*)(g_hbuf + (t & 1) * HH * BB) + w * 512;
            float4*       hdst = (float4*)h_s + w * 512;
#pragma unroll
            for (int i = 0; i < 16; i++)
                hdst[lane + 32 * i] = __ldcg(hin + lane + 32 * i);
        }
        __syncwarp();

        // ---- compute: 16 f32x2 accumulators over own 32-wide k-slice ----
        unsigned long long acc[4][4];
#pragma unroll
        for (int rp = 0; rp < 4; rp++)
#pragma unroll
            for (int j = 0; j < 4; j++) acc[rp][j] = 0ull;

#pragma unroll 4
        for (int k = 0; k < 32; k++) {
            float4 wv0 = *(const float4*)(wbase + k * 16);
            float4 wv1 = *(const float4*)(wbase + k * 16 + 4);
            float4 hv  = *(const float4*)(hbase + k * 32);
            unsigned long long wp0 = pk2(wv0.x, wv0.y);
            unsigned long long wp1 = pk2(wv0.z, wv0.w);
            unsigned long long wp2 = pk2(wv1.x, wv1.y);
            unsigned long long wp3 = pk2(wv1.z, wv1.w);
            unsigned long long h0 = pk2(hv.x, hv.x);
            unsigned long long h1 = pk2(hv.y, hv.y);
            unsigned long long h2 = pk2(hv.z, hv.z);
            unsigned long long h3 = pk2(hv.w, hv.w);
            ffma2(acc[0][0], wp0, h0); ffma2(acc[0][1], wp0, h1);
            ffma2(acc[0][2], wp0, h2); ffma2(acc[0][3], wp0, h3);
            ffma2(acc[1][0], wp1, h0); ffma2(acc[1][1], wp1, h1);
            ffma2(acc[1][2], wp1, h2); ffma2(acc[1][3], wp1, h3);
            ffma2(acc[2][0], wp2, h0); ffma2(acc[2][1], wp2, h1);
            ffma2(acc[2][2], wp2, h2); ffma2(acc[2][3], wp2, h3);
            ffma2(acc[3][0], wp3, h0); ffma2(acc[3][1], wp3, h1);
            ffma2(acc[3][2], wp3, h2); ffma2(acc[3][3], wp3, h3);
        }
        // swizzled partial store (16B chunks; slot = rp^(rowid&3), chunk low ^= xlow)
#pragma unroll
        for (int rp = 0; rp < 4; rp++) {
            int slot = rp ^ (rowid & 3);
            *(ulonglong2*)(psbase + slot * 8 + (0 ^ xlow)) =
                make_ulonglong2(acc[rp][0], acc[rp][1]);
            *(ulonglong2*)(psbase + slot * 8 + (4 ^ xlow)) =
                make_ulonglong2(acc[rp][2], acc[rp][3]);
        }
        __syncthreads();

        // ---- fused reduce + activation + publish (tid < 128) ----
        if (tid < 128) {
            float gs0 = 0.f, gs1 = 0.f, gs2 = 0.f, gs3 = 0.f;
#pragma unroll
            for (int kk = 0; kk < 16; kk++) {
                const float* pk = ps + kk * 512;
                gs0 += pk[gbase[0]];
                gs1 += pk[gbase[1]];
                gs2 += pk[gbase[2]];
                gs3 += pk[gbase[3]];
            }
            float gi = gs0 + pf4.x;
            float gf = gs1 + pf4.y;
            float gg = gs2 + pf4.z;
            float go = gs3 + pf4.w;
            float si = 1.0f / (1.0f + __expf(-gi));
            float sf = 1.0f / (1.0f + __expf(-gf));
            float so = 1.0f / (1.0f + __expf(-go));
            float tg = tanhf(gg);
            float c  = sf * c_s[tid] + si * tg;
            c_s[tid] = c;
            float h  = so * tanhf(c);
            g_hbuf[((t + 1) & 1) * HH * BB + (j0 + jl) * BB + ab] = h;  // coalesced per warp
            g_hout[((long)ab * LL + t) * HH + j0 + jl] = h;             // scattered 4B
            if (t + 1 < LL)
                pf4 = *(const float4*)(pre + preoff + (long)(t + 1) * G4);
        }
        __syncthreads();
        if (tid == 0) st_rel(myflag, (unsigned)(t + 1));
    }
}

// ---------------- blocked cumsum: P[b][t][d] = sum_{s<=t} hout[b][s][d] ----------------
__global__ void k_csum1() {      // grid (16, BB): chunk c covers t in [c*64, c*64+64)
    int c = blockIdx.x, b = blockIdx.y;
    int d = threadIdx.x;
    const float* s0 = g_hout + ((long)b * LL + c * 64) * HH + d;
    const float* s1 = s0 + 256;
    float* d0 = g_P + ((long)b * LL + c * 64) * HH + d;
    float* d1 = d0 + 256;
    float a0 = 0.f, a1 = 0.f;
#pragma unroll 8
    for (int t = 0; t < 64; t++) {
        a0 += s0[t * HH]; d0[t * HH] = a0;
        a1 += s1[t * HH]; d1[t * HH] = a1;
    }
    g_csum[((long)b * 16 + c) * HH + d]       = a0;
    g_csum[((long)b * 16 + c) * HH + d + 256] = a1;
}

__global__ void k_csum2() {      // grid (15, BB): chunks 1..15 add exclusive offsets
    int c = blockIdx.x + 1, b = blockIdx.y;
    int d = threadIdx.x;
    float o0 = 0.f, o1 = 0.f;
    for (int cc = 0; cc < c; cc++) {
        o0 += g_csum[((long)b * 16 + cc) * HH + d];
        o1 += g_csum[((long)b * 16 + cc) * HH + d + 256];
    }
    float* d0 = g_P + ((long)b * LL + c * 64) * HH + d;
    float* d1 = d0 + 256;
#pragma unroll 8
    for (int t = 0; t < 64; t++) {
        d0[t * HH] += o0;
        d1[t * HH] += o1;
    }
}

// ---------------- banded online-softmax attention ----------------
__device__ __forceinline__ void upd(float& m, float& l, float4* acc, float sc, const float4* ov) {
    if (sc <= m) {
        float e = __expf(sc - m);
        l += e;
#pragma unroll
        for (int j = 0; j < 4; j++) {
            acc[j].x += e * ov[j].x; acc[j].y += e * ov[j].y;
            acc[j].z += e * ov[j].z; acc[j].w += e * ov[j].w;
        }
    } else {
        float coef = __expf(m - sc);
        l = l * coef + 1.0f;
#pragma unroll
        for (int j = 0; j < 4; j++) {
            acc[j].x = acc[j].x * coef + ov[j].x; acc[j].y = acc[j].y * coef + ov[j].y;
            acc[j].z = acc[j].z * coef + ov[j].z; acc[j].w = acc[j].w * coef + ov[j].w;
        }
        m = sc;
    }
}

__global__ void k_attn() {
    int warp = (blockIdx.x * blockDim.x + threadIdx.x) >> 5;  // 0..16383
    int lane = threadIdx.x & 31;
    int b  = warp >> 9;
    int tp = warp & 511;
    int t0 = tp * 2, t1 = t0 + 1;

    const float* mb = g_mlp  + (long)b * LL * DD;
    const float* ob = g_hout + (long)b * LL * HH;

    float4 q0[4], q1[4], acc0[4], acc1[4];
#pragma unroll
    for (int j = 0; j < 4; j++) {
        q0[j] = *(const float4*)(mb + (long)t0 * DD + lane * 4 + j * 128);
        q1[j] = *(const float4*)(mb + (long)t1 * DD + lane * 4 + j * 128);
        acc0[j] = make_float4(0.f, 0.f, 0.f, 0.f);
        acc1[j] = make_float4(0.f, 0.f, 0.f, 0.f);
    }
    float m0 = -1e30f, m1 = -1e30f, l0 = 0.0f, l1 = 0.0f;

    int slo = t0 - (WIN - 1); if (slo < 0) slo = 0;
    for (int s = slo; s <= t1; s++) {
        float4 ov[4];
        const float* op = ob + (long)s * HH + lane * 4;
#pragma unroll
        for (int j = 0; j < 4; j++) ov[j] = *(const float4*)(op + j * 128);
        float d0 = 0.f, d1 = 0.f;
#pragma unroll
        for (int j = 0; j < 4; j++) {
            d0 += q0[j].x * ov[j].x + q0[j].y * ov[j].y + q0[j].z * ov[j].z + q0[j].w * ov[j].w;
            d1 += q1[j].x * ov[j].x + q1[j].y * ov[j].y + q1[j].z * ov[j].z + q1[j].w * ov[j].w;
        }
#pragma unroll
        for (int off = 16; off; off >>= 1) {
            d0 += __shfl_xor_sync(0xFFFFFFFFu, d0, off);
            d1 += __shfl_xor_sync(0xFFFFFFFFu, d1, off);
        }
        if (s <= t0) {
            float sc = d0 * __expf(-0.6f * (float)(t0 - s));
            upd(m0, l0, acc0, sc, ov);
        }
        if (s >= t1 - (WIN - 1)) {
            float sc = d1 * __expf(-0.6f * (float)(t1 - s));
            upd(m1, l1, acc1, sc, ov);
        }
    }
    // tails: all s <= t-WIN contribute exactly exp(-m) each (fp32-exact vs reference)
    if (t0 >= WIN) {
        float cnt = (float)(t0 - (WIN - 1));
        const float* pp = g_P + ((long)b * LL + (t0 - WIN)) * HH + lane * 4;
        float4 pv[4];
#pragma unroll
        for (int j = 0; j < 4; j++) pv[j] = *(const float4*)(pp + j * 128);
        if (0.0f <= m0) {
            float e = __expf(-m0);
            l0 += cnt * e;
#pragma unroll
            for (int j = 0; j < 4; j++) {
                acc0[j].x += e * pv[j].x; acc0[j].y += e * pv[j].y;
                acc0[j].z += e * pv[j].z; acc0[j].w += e * pv[j].w;
            }
        } else {
            float coef = __expf(m0);
            l0 = l0 * coef + cnt;
#pragma unroll
            for (int j = 0; j < 4; j++) {
                acc0[j].x = acc0[j].x * coef + pv[j].x; acc0[j].y = acc0[j].y * coef + pv[j].y;
                acc0[j].z = acc0[j].z * coef + pv[j].z; acc0[j].w = acc0[j].w * coef + pv[j].w;
            }
            m0 = 0.0f;
        }
    }
    if (t1 >= WIN) {
        float cnt = (float)(t1 - (WIN - 1));
        const float* pp = g_P + ((long)b * LL + (t1 - WIN)) * HH + lane * 4;
        float4 pv[4];
#pragma unroll
        for (int j = 0; j < 4; j++) pv[j] = *(const float4*)(pp + j * 128);
        if (0.0f <= m1) {
            float e = __expf(-m1);
            l1 += cnt * e;
#pragma unroll
            for (int j = 0; j < 4; j++) {
                acc1[j].x += e * pv[j].x; acc1[j].y += e * pv[j].y;
                acc1[j].z += e * pv[j].z; acc1[j].w += e * pv[j].w;
            }
        } else {
            float coef = __expf(m1);
            l1 = l1 * coef + cnt;
#pragma unroll
            for (int j = 0; j < 4; j++) {
                acc1[j].x = acc1[j].x * coef + pv[j].x; acc1[j].y = acc1[j].y * coef + pv[j].y;
                acc1[j].z = acc1[j].z * coef + pv[j].z; acc1[j].w = acc1[j].w * coef + pv[j].w;
            }
            m1 = 0.0f;
        }
    }

    float inv0 = 1.0f / l0, inv1 = 1.0f / l1;
    float* w0 = g_wgt + ((long)b * LL + t0) * HH + lane * 4;
    float* w1 = g_wgt + ((long)b * LL + t1) * HH + lane * 4;
#pragma unroll
    for (int j = 0; j < 4; j++) {
        float4 r0 = make_float4(acc0[j].x * inv0, acc0[j].y * inv0, acc0[j].z * inv0, acc0[j].w * inv0);
        float4 r1 = make_float4(acc1[j].x * inv1, acc1[j].y * inv1, acc1[j].z * inv1, acc1[j].w * inv1);
        *(float4*)(w0 + j * 128) = r0;
        *(float4*)(w1 + j * 128) = r1;
    }
}

// ---------------- launch ----------------
extern "C" void kernel_launch(void* const* d_in, const int* in_sizes, int n_in,
                              void* d_out, int out_size) {
    const float* x        = (const float*)d_in[0];
    const int*   concepts = (const int*)  d_in[1];
    const float* emb      = (const float*)d_in[2];
    const float* Wih      = (const float*)d_in[3];
    const float* Whh      = (const float*)d_in[4];
    const float* bih      = (const float*)d_in[5];
    const float* bhh      = (const float*)d_in[6];
    const float* Wm       = (const float*)d_in[7];
    const float* bm       = (const float*)d_in[8];
    const float* W1       = (const float*)d_in[9];
    const float* b1       = (const float*)d_in[10];
    const float* W2       = (const float*)d_in[11];
    const float* b2       = (const float*)d_in[12];
    float* out = (float*)d_out;

    float *p_pre, *p_cpart, *p_mlp, *p_wgt, *p_h1;
    cudaGetSymbolAddress((void**)&p_pre,   g_pre);
    cudaGetSymbolAddress((void**)&p_cpart, g_cpart);
    cudaGetSymbolAddress((void**)&p_mlp,   g_mlp);
    cudaGetSymbolAddress((void**)&p_wgt,   g_wgt);
    cudaGetSymbolAddress((void**)&p_h1,    g_h1);

    // smem: w_t 32KB + h_s 64KB + ps 32KB + c_s 512B = ~128.5KB
    const int lstm_smem = (512 * 16 + 512 * 32 + 16 * 512 + 128) * 4;
    cudaFuncSetAttribute(k_lstm, cudaFuncAttributeMaxDynamicSharedMemorySize, lstm_smem);

    const int M = BB * LL;   // 32768

    k_init<<<128, 256>>>();
    k_cpart<<<BB * 8, 256>>>(emb, concepts, Wih, bih, bhh);
    // pre = x @ WihA^T + cpart (PERMUTED output: [b][t][j*4+gate])
    k_gemm<false, true><<<dim3(G4 / 128, M / 128), 256>>>(x, DD, Wih, 2 * DD, nullptr, p_cpart,
                                                          p_pre, G4, G4, DD);
    // mlp = x @ Wm^T + bm
    k_gemm<false, false><<<dim3(DD / 128, M / 128), 256>>>(x, DD, Wm, DD, bm, nullptr,
                                                           p_mlp, DD, DD, DD);
    // LSTM recurrence
    k_lstm<<<NCTA_LSTM, 256, lstm_smem>>>(p_pre, Whh);
    // blocked prefix sums of h over time
    k_csum1<<<dim3(16, BB), 256>>>();
    k_csum2<<<dim3(15, BB), 256>>>();
    // attention
    k_attn<<<2048, 256>>>();
    // h1 = relu(weighted @ W1^T + b1)
    k_gemm<true, false><<<dim3(FF / 128, M / 128), 256>>>(p_wgt, HH, W1, HH, b1, nullptr,
                                                          p_h1, FF, FF, HH);
    // res = h1 @ W2^T + b2
    k_gemm<false, false><<<dim3(1, M / 128), 256>>>(p_h1, FF, W2, FF, b2, nullptr,
                                                    out, OUTD, OUTD, FF);
}

// round 10
// speedup vs baseline: 1.2259x; 1.2259x over previous
#include <cuda_runtime.h>
#include <cuda_bf16.h>
#include <math.h>
#include <stdint.h>

// Problem dims
#define BB   32
#define LL   1024
#define DD   512
#define HH   512
#define G4   2048
#define FF   256
#define OUTD 100
#define NCTA_LSTM 128
#define WIN  64          // exact softmax window; beyond this exp(score*decay - m) == exp(-m) in fp32

// ---------------- scratch (device globals; no allocation) ----------------
__device__ float g_pre  [BB * LL * G4];     // gates pre-activation, PERMUTED: [b][t][j*4+gate]
__device__ float g_cpart[BB * G4];          // concept part + biases (original gate order)
__device__ float g_hout [BB * LL * HH];     // LSTM hidden states
__device__ float g_hbuf [2 * HH * BB];      // h double buffer [buf][k][b]
__device__ float g_mlp  [BB * LL * DD];     // mlp_out
__device__ float g_P    [BB * LL * HH];     // cumsum of hout over t
__device__ float g_csum [BB * 16 * HH];     // per-chunk sums for blocked scan
__device__ float g_wgt  [BB * LL * HH];     // attention output
__device__ float g_h1   [BB * LL * FF];     // relu(W1 ...)
__device__ unsigned g_flags[NCTA_LSTM * 32]; // per-CTA step flags, 128B apart

// bf16 hi|lo split operands (stride 1024: cols 0..511 = hi, 512..1023 = lo)
__device__ __nv_bfloat16 g_xs  [BB * LL * 1024];
__device__ __nv_bfloat16 g_wgts[BB * LL * 1024];
__device__ __nv_bfloat16 g_wihs[G4 * 1024];
__device__ __nv_bfloat16 g_wms [DD * 1024];
__device__ __nv_bfloat16 g_w1s [FF * 1024];

// ---------------- PTX helpers ----------------
__device__ __forceinline__ unsigned long long pk2(float lo, float hi) {
    unsigned long long r;
    asm("mov.b64 %0, {%1, %2};" : "=l"(r) : "f"(lo), "f"(hi));
    return r;
}
__device__ __forceinline__ void ffma2(unsigned long long& d, unsigned long long a,
                                      unsigned long long b) {
    asm("fma.rn.f32x2 %0, %1, %2, %0;" : "+l"(d) : "l"(a), "l"(b));
}
__device__ __forceinline__ unsigned ld_acq(const unsigned* p) {
    unsigned v;
    asm volatile("ld.acquire.gpu.global.u32 %0, [%1];" : "=r"(v) : "l"(p));
    return v;
}
__device__ __forceinline__ void st_rel(unsigned* p, unsigned v) {
    asm volatile("st.release.gpu.global.u32 [%0], %1;" :: "l"(p), "r"(v));
}
__device__ __forceinline__ uint32_t s2u(const void* p) {
    uint32_t a;
    asm("{ .reg .u64 t; cvta.to.shared.u64 t, %1; cvt.u32.u64 %0, t; }" : "=r"(a) : "l"(p));
    return a;
}
__device__ __forceinline__ void ldm_x4(uint32_t* r, uint32_t addr) {
    asm volatile("ldmatrix.sync.aligned.m8n8.x4.shared.b16 {%0,%1,%2,%3}, [%4];"
                 : "=r"(r[0]), "=r"(r[1]), "=r"(r[2]), "=r"(r[3]) : "r"(addr));
}
__device__ __forceinline__ void mma16816(float* d, const uint32_t* a, const uint32_t* b) {
    asm volatile("mma.sync.aligned.m16n8k16.row.col.f32.bf16.bf16.f32 "
                 "{%0,%1,%2,%3}, {%4,%5,%6,%7}, {%8,%9}, {%0,%1,%2,%3};"
                 : "+f"(d[0]), "+f"(d[1]), "+f"(d[2]), "+f"(d[3])
                 : "r"(a[0]), "r"(a[1]), "r"(a[2]), "r"(a[3]), "r"(b[0]), "r"(b[1]));
}

// ---------------- init ----------------
__global__ void k_init() {
    int i = blockIdx.x * 256 + threadIdx.x;
    if (i < 2 * HH * BB) g_hbuf[i] = 0.0f;
    if (i < NCTA_LSTM * 32) g_flags[i] = 0u;
}

// ---------------- fp32 -> bf16 hi|lo split; dst stride 1024, 512-col source block ----
__global__ void k_split(const float* __restrict__ s, int ld, __nv_bfloat16* __restrict__ d) {
    long i = ((long)blockIdx.x * 256 + threadIdx.x) * 4;
    int r = (int)(i >> 9), c = (int)(i & 511);
    float4 v = *(const float4*)(s + (long)r * ld + c);
    float vv[4] = {v.x, v.y, v.z, v.w};
    __nv_bfloat16 h[4], l[4];
#pragma unroll
    for (int j = 0; j < 4; j++) {
        h[j] = __float2bfloat16(vv[j]);
        l[j] = __float2bfloat16(vv[j] - __bfloat162float(h[j]));
    }
    __nv_bfloat16* dh = d + (long)r * 1024 + c;
    *(__nv_bfloat162*)(dh)       = __nv_bfloat162(h[0], h[1]);
    *(__nv_bfloat162*)(dh + 2)   = __nv_bfloat162(h[2], h[3]);
    *(__nv_bfloat162*)(dh + 512) = __nv_bfloat162(l[0], l[1]);
    *(__nv_bfloat162*)(dh + 514) = __nv_bfloat162(l[2], l[3]);
}

// ---------------- cpart[b][g] = emb[concepts[b]] . Wih[g][512:1024] + bih[g] + bhh[g] --------
__global__ void k_cpart(const float* __restrict__ emb, const int* __restrict__ concepts,
                        const float* __restrict__ Wih, const float* __restrict__ bih,
                        const float* __restrict__ bhh) {
    int b = blockIdx.x >> 3;
    int g = ((blockIdx.x & 7) << 8) + threadIdx.x;
    const float4* e = (const float4*)(emb + (long)concepts[b] * HH);
    const float4* w = (const float4*)(Wih + (long)g * (2 * DD) + DD);
    float acc = bih[g] + bhh[g];
#pragma unroll 4
    for (int k = 0; k < HH / 4; k++) {
        float4 wv = __ldg(w + k);
        float4 ev = __ldg(e + k);
        acc += wv.x * ev.x + wv.y * ev.y + wv.z * ev.z + wv.w * ev.w;
    }
    g_cpart[b * G4 + g] = acc;
}

// ---------------- bf16-split tensor-core GEMM (mma.sync m16n8k16) ----------------
// C[M,N] = A[M,512] * B[N,512]^T computed as Ah*Bh + Al*Bh + Ah*Bl over 24 K-chunks
// of 64 from the [hi|lo] split arrays (stride 1024). Tile 128x128, 8 warps 2m x 4n,
// warp tile 64x32. smem rows padded to 72 bf16 -> ldmatrix conflict-free.
template<int RELU, int PERM>
__global__ void __launch_bounds__(256, 2)
k_mma(const __nv_bfloat16* __restrict__ A, const __nv_bfloat16* __restrict__ B,
      const float* __restrict__ bias, const float* __restrict__ rowvec,
      float* __restrict__ C, int ldc, int N) {
    __shared__ __nv_bfloat16 sA[128 * 72];
    __shared__ __nv_bfloat16 sB[128 * 72];
    int tid = threadIdx.x, wid = tid >> 5, lane = tid & 31;
    int wm = (wid >> 2) * 64, wn = (wid & 3) * 32;

    float d[4][4][4];
#pragma unroll
    for (int i = 0; i < 4; i++)
#pragma unroll
        for (int j = 0; j < 4; j++)
#pragma unroll
            for (int q = 0; q < 4; q++) d[i][j][q] = 0.0f;

    uint32_t sAu = s2u(sA), sBu = s2u(sB);
    // ldmatrix lane address components (bytes)
    uint32_t aRow = (uint32_t)(((wm + (lane & 15)) * 72 + (lane >> 4) * 8) * 2);
    uint32_t bRow = (uint32_t)(((wn + (lane >> 4) * 8 + (lane & 7)) * 72 + ((lane >> 3) & 1) * 8) * 2);

    long abase = (long)(blockIdx.y * 128) * 1024;
    long bbase = (long)(blockIdx.x * 128) * 1024;

    for (int kc = 0; kc < 24; kc++) {
        int ao = (kc < 8) ? kc * 64 : (kc < 16) ? 512 + (kc - 8) * 64 : (kc - 16) * 64;
        int bo = (kc < 8) ? kc * 64 : (kc < 16) ? (kc - 8) * 64 : 512 + (kc - 16) * 64;
#pragma unroll
        for (int it = 0; it < 4; it++) {
            int idx = tid + it * 256;
            int r = idx >> 3, cc = (idx & 7) * 8;
            *(uint4*)(sA + r * 72 + cc) = *(const uint4*)(A + abase + (long)r * 1024 + ao + cc);
            *(uint4*)(sB + r * 72 + cc) = *(const uint4*)(B + bbase + (long)r * 1024 + bo + cc);
        }
        __syncthreads();
#pragma unroll
        for (int ks = 0; ks < 4; ks++) {
            uint32_t af[4][4], bq[4], bf[4][2];
#pragma unroll
            for (int mi = 0; mi < 4; mi++)
                ldm_x4(af[mi], sAu + aRow + (uint32_t)((mi * 16 * 72 + ks * 16) * 2));
#pragma unroll
            for (int p = 0; p < 2; p++) {
                ldm_x4(bq, sBu + bRow + (uint32_t)((p * 16 * 72 + ks * 16) * 2));
                bf[p * 2][0]     = bq[0]; bf[p * 2][1]     = bq[1];
                bf[p * 2 + 1][0] = bq[2]; bf[p * 2 + 1][1] = bq[3];
            }
#pragma unroll
            for (int mi = 0; mi < 4; mi++)
#pragma unroll
                for (int nj = 0; nj < 4; nj++)
                    mma16816(d[mi][nj], af[mi], bf[nj]);
        }
        __syncthreads();
    }

    // epilogue: direct register -> global
    int g = lane >> 2, t2 = (lane & 3) * 2;
#pragma unroll
    for (int mi = 0; mi < 4; mi++) {
#pragma unroll
        for (int half = 0; half < 2; half++) {
            int mg = blockIdx.y * 128 + wm + mi * 16 + g + half * 8;
            const float* rv = rowvec ? (rowvec + (long)(mg >> 10) * N) : nullptr;
            float* crow = C + (long)mg * ldc;
#pragma unroll
            for (int nj = 0; nj < 4; nj++) {
                int n = blockIdx.x * 128 + wn + nj * 8 + t2;
                float v0 = d[mi][nj][half * 2];
                float v1 = d[mi][nj][half * 2 + 1];
                if (bias) { v0 += bias[n]; v1 += bias[n + 1]; }
                if (rv)   { v0 += rv[n];   v1 += rv[n + 1]; }
                if (RELU) { v0 = fmaxf(v0, 0.0f); v1 = fmaxf(v1, 0.0f); }
                if (PERM) {
                    crow[(((n)     & 511) << 2) | ((n)     >> 9)] = v0;
                    crow[(((n + 1) & 511) << 2) | ((n + 1) >> 9)] = v1;
                } else {
                    *(float2*)(crow + n) = make_float2(v0, v1);
                }
            }
        }
    }
}

// ---------------- scalar SGEMM (FF2 only: N=100, K=256) ----------------
template<bool RELU>
__global__ void k_gemm(const float* __restrict__ A, int lda,
                       const float* __restrict__ W, int ldw,
                       const float* __restrict__ bias,
                       float* __restrict__ C, int ldc,
                       int N, int K) {
    __shared__ float As[16 * 132];
    __shared__ float Bs[16 * 132];
    int tid = threadIdx.x;
    int bx = blockIdx.x, by = blockIdx.y;
    int tx = tid & 15, ty = tid >> 4;

    float acc[8][8];
#pragma unroll
    for (int i = 0; i < 8; i++)
#pragma unroll
        for (int j = 0; j < 8; j++) acc[i][j] = 0.0f;

    int row = tid >> 2;
    int kl  = (tid & 3) * 4;
    const float* Abase = A + (long)(by * 128 + row) * lda + kl;
    int n0l = bx * 128 + row, n1l = n0l + 64;
    const float* W0 = (n0l < N) ? (W + (long)n0l * ldw + kl) : nullptr;
    const float* W1 = (n1l < N) ? (W + (long)n1l * ldw + kl) : nullptr;

    for (int kt = 0; kt < K; kt += 16) {
        float4 a0 = *(const float4*)(Abase + kt);
        float4 a1 = *(const float4*)(Abase + kt + (long)64 * lda);
        float4 b0 = make_float4(0.f, 0.f, 0.f, 0.f);
        float4 b1 = make_float4(0.f, 0.f, 0.f, 0.f);
        if (W0) b0 = *(const float4*)(W0 + kt);
        if (W1) b1 = *(const float4*)(W1 + kt);
#pragma unroll
        for (int q = 0; q < 4; q++) {
            float av0 = q == 0 ? a0.x : q == 1 ? a0.y : q == 2 ? a0.z : a0.w;
            float av1 = q == 0 ? a1.x : q == 1 ? a1.y : q == 2 ? a1.z : a1.w;
            float bv0 = q == 0 ? b0.x : q == 1 ? b0.y : q == 2 ? b0.z : b0.w;
            float bv1 = q == 0 ? b1.x : q == 1 ? b1.y : q == 2 ? b1.z : b1.w;
            As[(kl + q) * 132 + row]      = av0;
            As[(kl + q) * 132 + row + 64] = av1;
            Bs[(kl + q) * 132 + row]      = bv0;
            Bs[(kl + q) * 132 + row + 64] = bv1;
        }
        __syncthreads();
#pragma unroll
        for (int k = 0; k < 16; k++) {
            float4 av0 = *(const float4*)&As[k * 132 + ty * 8];
            float4 av1 = *(const float4*)&As[k * 132 + ty * 8 + 4];
            float4 bv0 = *(const float4*)&Bs[k * 132 + tx * 8];
            float4 bv1 = *(const float4*)&Bs[k * 132 + tx * 8 + 4];
            float a[8] = {av0.x, av0.y, av0.z, av0.w, av1.x, av1.y, av1.z, av1.w};
            float b[8] = {bv0.x, bv0.y, bv0.z, bv0.w, bv1.x, bv1.y, bv1.z, bv1.w};
#pragma unroll
            for (int i = 0; i < 8; i++)
#pragma unroll
                for (int j = 0; j < 8; j++) acc[i][j] += a[i] * b[j];
        }
        __syncthreads();
    }

    int m0 = by * 128 + ty * 8, nn0 = bx * 128 + tx * 8;
#pragma unroll
    for (int i = 0; i < 8; i++) {
        int m = m0 + i;
#pragma unroll
        for (int j = 0; j < 8; j++) {
            int n = nn0 + j;
            if (n < N) {
                float v = acc[i][j];
                if (bias) v += bias[n];
                if (RELU) v = fmaxf(v, 0.0f);
                C[(long)m * ldc + n] = v;
            }
        }
    }
}

// ---------------- persistent LSTM (per-warp producer polling, fused reduce+act) --------
__global__ void __launch_bounds__(256, 1)
k_lstm(const float* __restrict__ pre, const float* __restrict__ Whh) {
    extern __shared__ float sm[];
    float* w_t = sm;                   // [512][16]
    float* h_s = w_t + 512 * 16;       // [512][32]
    float* ps  = h_s + 512 * 32;       // [16][512] swizzled partials
    float* c_s = ps + 16 * 512;        // [128]

    int tid  = threadIdx.x;
    int j0   = blockIdx.x * 4;
    int w    = tid >> 5;
    int lane = tid & 31;

    for (int i = tid; i < 16 * 512; i += 256) {
        int lr = i & 15, k = i >> 4;
        int grow = ((lr >> 2) << 9) + j0 + (lr & 3);
        w_t[k * 16 + lr] = Whh[(long)grow * HH + k];
    }
    if (tid < 128) c_s[tid] = 0.0f;

    int ks  = tid >> 4;
    int l16 = tid & 15;
    int rt  = l16 >> 3;
    int bt  = l16 & 7;
    int rowid = rt * 8 + bt;
    int xlow  = ((rowid >> 2) & 1) << 2;
    const float* wbase = w_t + (ks * 32) * 16 + rt * 8;
    const float* hbase = h_s + (ks * 32) * 32 + bt * 4;
    float* psbase = ps + ks * 512 + rowid * 32;

    int jl = tid >> 5, ab = tid & 31;
    long preoff = (long)ab * LL * G4 + (j0 + jl) * 4;
    int low_r = (((ab & 3) << 1) | (jl & 1)) ^ (((ab >> 4) & 1) << 2);
    int gbase[4];
#pragma unroll
    for (int g = 0; g < 4; g++) {
        int rp   = (g * 2 + (jl >> 1)) & 3;
        int slot = rp ^ ((ab >> 2) & 3);
        gbase[g] = (g >> 1) * 256 + (ab >> 2) * 32 + slot * 8 + low_r;
    }

    unsigned* myflag = &g_flags[blockIdx.x * 32];
    const unsigned* pollflag = &g_flags[(w * 16 + (lane & 15)) * 32];

    __syncthreads();

    float4 pf4 = make_float4(0.f, 0.f, 0.f, 0.f);
    if (tid < 128) pf4 = *(const float4*)(pre + preoff);

    for (int t = 0; t < LL; t++) {
        while (ld_acq(pollflag) < (unsigned)t) { }
        __syncwarp();
        {
            const float4* hin  = (const float4*)(g_hbuf + (t & 1) * HH * BB) + w * 512;
            float4*       hdst = (float4*)h_s + w * 512;
#pragma unroll
            for (int i = 0; i < 16; i++)
                hdst[lane + 32 * i] = __ldcg(hin + lane + 32 * i);
        }
        __syncwarp();

        unsigned long long acc[4][4];
#pragma unroll
        for (int rp = 0; rp < 4; rp++)
#pragma unroll
            for (int j = 0; j < 4; j++) acc[rp][j] = 0ull;

#pragma unroll 4
        for (int k = 0; k < 32; k++) {
            float4 wv0 = *(const float4*)(wbase + k * 16);
            float4 wv1 = *(const float4*)(wbase + k * 16 + 4);
            float4 hv  = *(const float4*)(hbase + k * 32);
            unsigned long long wp0 = pk2(wv0.x, wv0.y);
            unsigned long long wp1 = pk2(wv0.z, wv0.w);
            unsigned long long wp2 = pk2(wv1.x, wv1.y);
            unsigned long long wp3 = pk2(wv1.z, wv1.w);
            unsigned long long h0 = pk2(hv.x, hv.x);
            unsigned long long h1 = pk2(hv.y, hv.y);
            unsigned long long h2 = pk2(hv.z, hv.z);
            unsigned long long h3 = pk2(hv.w, hv.w);
            ffma2(acc[0][0], wp0, h0); ffma2(acc[0][1], wp0, h1);
            ffma2(acc[0][2], wp0, h2); ffma2(acc[0][3], wp0, h3);
            ffma2(acc[1][0], wp1, h0); ffma2(acc[1][1], wp1, h1);
            ffma2(acc[1][2], wp1, h2); ffma2(acc[1][3], wp1, h3);
            ffma2(acc[2][0], wp2, h0); ffma2(acc[2][1], wp2, h1);
            ffma2(acc[2][2], wp2, h2); ffma2(acc[2][3], wp2, h3);
            ffma2(acc[3][0], wp3, h0); ffma2(acc[3][1], wp3, h1);
            ffma2(acc[3][2], wp3, h2); ffma2(acc[3][3], wp3, h3);
        }
#pragma unroll
        for (int rp = 0; rp < 4; rp++) {
            int slot = rp ^ (rowid & 3);
            *(ulonglong2*)(psbase + slot * 8 + (0 ^ xlow)) =
                make_ulonglong2(acc[rp][0], acc[rp][1]);
            *(ulonglong2*)(psbase + slot * 8 + (4 ^ xlow)) =
                make_ulonglong2(acc[rp][2], acc[rp][3]);
        }
        __syncthreads();

        if (tid < 128) {
            float gs0 = 0.f, gs1 = 0.f, gs2 = 0.f, gs3 = 0.f;
#pragma unroll
            for (int kk = 0; kk < 16; kk++) {
                const float* pk = ps + kk * 512;
                gs0 += pk[gbase[0]];
                gs1 += pk[gbase[1]];
                gs2 += pk[gbase[2]];
                gs3 += pk[gbase[3]];
            }
            float gi = gs0 + pf4.x;
            float gf = gs1 + pf4.y;
            float gg = gs2 + pf4.z;
            float go = gs3 + pf4.w;
            float si = __fdividef(1.0f, 1.0f + __expf(-gi));
            float sf = __fdividef(1.0f, 1.0f + __expf(-gf));
            float so = __fdividef(1.0f, 1.0f + __expf(-go));
            float ag = fabsf(gg);
            float eg = __expf(-2.0f * ag);
            float tg = copysignf(__fdividef(1.0f - eg, 1.0f + eg), gg);
            float c  = sf * c_s[tid] + si * tg;
            c_s[tid] = c;
            float ac = fabsf(c);
            float ec = __expf(-2.0f * ac);
            float tc = copysignf(__fdividef(1.0f - ec, 1.0f + ec), c);
            float h  = so * tc;
            g_hbuf[((t + 1) & 1) * HH * BB + (j0 + jl) * BB + ab] = h;
            g_hout[((long)ab * LL + t) * HH + j0 + jl] = h;
            if (t + 1 < LL)
                pf4 = *(const float4*)(pre + preoff + (long)(t + 1) * G4);
        }
        __syncthreads();
        if (tid == 0) st_rel(myflag, (unsigned)(t + 1));
    }
}

// ---------------- blocked cumsum ----------------
__global__ void k_csum1() {
    int c = blockIdx.x, b = blockIdx.y;
    int d = threadIdx.x;
    const float* s0 = g_hout + ((long)b * LL + c * 64) * HH + d;
    const float* s1 = s0 + 256;
    float* d0 = g_P + ((long)b * LL + c * 64) * HH + d;
    float* d1 = d0 + 256;
    float a0 = 0.f, a1 = 0.f;
#pragma unroll 8
    for (int t = 0; t < 64; t++) {
        a0 += s0[t * HH]; d0[t * HH] = a0;
        a1 += s1[t * HH]; d1[t * HH] = a1;
    }
    g_csum[((long)b * 16 + c) * HH + d]       = a0;
    g_csum[((long)b * 16 + c) * HH + d + 256] = a1;
}

__global__ void k_csum2() {
    int c = blockIdx.x + 1, b = blockIdx.y;
    int d = threadIdx.x;
    float o0 = 0.f, o1 = 0.f;
    for (int cc = 0; cc < c; cc++) {
        o0 += g_csum[((long)b * 16 + cc) * HH + d];
        o1 += g_csum[((long)b * 16 + cc) * HH + d + 256];
    }
    float* d0 = g_P + ((long)b * LL + c * 64) * HH + d;
    float* d1 = d0 + 256;
#pragma unroll 8
    for (int t = 0; t < 64; t++) {
        d0[t * HH] += o0;
        d1[t * HH] += o1;
    }
}

// ---------------- banded online-softmax attention ----------------
__device__ __forceinline__ void upd(float& m, float& l, float4* acc, float sc, const float4* ov) {
    if (sc <= m) {
        float e = __expf(sc - m);
        l += e;
#pragma unroll
        for (int j = 0; j < 4; j++) {
            acc[j].x += e * ov[j].x; acc[j].y += e * ov[j].y;
            acc[j].z += e * ov[j].z; acc[j].w += e * ov[j].w;
        }
    } else {
        float coef = __expf(m - sc);
        l = l * coef + 1.0f;
#pragma unroll
        for (int j = 0; j < 4; j++) {
            acc[j].x = acc[j].x * coef + ov[j].x; acc[j].y = acc[j].y * coef + ov[j].y;
            acc[j].z = acc[j].z * coef + ov[j].z; acc[j].w = acc[j].w * coef + ov[j].w;
        }
        m = sc;
    }
}

__global__ void k_attn() {
    int warp = (blockIdx.x * blockDim.x + threadIdx.x) >> 5;
    int lane = threadIdx.x & 31;
    int b  = warp >> 9;
    int tp = warp & 511;
    int t0 = tp * 2, t1 = t0 + 1;

    const float* mb = g_mlp  + (long)b * LL * DD;
    const float* ob = g_hout + (long)b * LL * HH;

    float4 q0[4], q1[4], acc0[4], acc1[4];
#pragma unroll
    for (int j = 0; j < 4; j++) {
        q0[j] = *(const float4*)(mb + (long)t0 * DD + lane * 4 + j * 128);
        q1[j] = *(const float4*)(mb + (long)t1 * DD + lane * 4 + j * 128);
        acc0[j] = make_float4(0.f, 0.f, 0.f, 0.f);
        acc1[j] = make_float4(0.f, 0.f, 0.f, 0.f);
    }
    float m0 = -1e30f, m1 = -1e30f, l0 = 0.0f, l1 = 0.0f;

    int slo = t0 - (WIN - 1); if (slo < 0) slo = 0;
    for (int s = slo; s <= t1; s++) {
        float4 ov[4];
        const float* op = ob + (long)s * HH + lane * 4;
#pragma unroll
        for (int j = 0; j < 4; j++) ov[j] = *(const float4*)(op + j * 128);
        float d0 = 0.f, d1 = 0.f;
#pragma unroll
        for (int j = 0; j < 4; j++) {
            d0 += q0[j].x * ov[j].x + q0[j].y * ov[j].y + q0[j].z * ov[j].z + q0[j].w * ov[j].w;
            d1 += q1[j].x * ov[j].x + q1[j].y * ov[j].y + q1[j].z * ov[j].z + q1[j].w * ov[j].w;
        }
#pragma unroll
        for (int off = 16; off; off >>= 1) {
            d0 += __shfl_xor_sync(0xFFFFFFFFu, d0, off);
            d1 += __shfl_xor_sync(0xFFFFFFFFu, d1, off);
        }
        if (s <= t0) {
            float sc = d0 * __expf(-0.6f * (float)(t0 - s));
            upd(m0, l0, acc0, sc, ov);
        }
        if (s >= t1 - (WIN - 1)) {
            float sc = d1 * __expf(-0.6f * (float)(t1 - s));
            upd(m1, l1, acc1, sc, ov);
        }
    }
    if (t0 >= WIN) {
        float cnt = (float)(t0 - (WIN - 1));
        const float* pp = g_P + ((long)b * LL + (t0 - WIN)) * HH + lane * 4;
        float4 pv[4];
#pragma unroll
        for (int j = 0; j < 4; j++) pv[j] = *(const float4*)(pp + j * 128);
        if (0.0f <= m0) {
            float e = __expf(-m0);
            l0 += cnt * e;
#pragma unroll
            for (int j = 0; j < 4; j++) {
                acc0[j].x += e * pv[j].x; acc0[j].y += e * pv[j].y;
                acc0[j].z += e * pv[j].z; acc0[j].w += e * pv[j].w;
            }
        } else {
            float coef = __expf(m0);
            l0 = l0 * coef + cnt;
#pragma unroll
            for (int j = 0; j < 4; j++) {
                acc0[j].x = acc0[j].x * coef + pv[j].x; acc0[j].y = acc0[j].y * coef + pv[j].y;
                acc0[j].z = acc0[j].z * coef + pv[j].z; acc0[j].w = acc0[j].w * coef + pv[j].w;
            }
            m0 = 0.0f;
        }
    }
    if (t1 >= WIN) {
        float cnt = (float)(t1 - (WIN - 1));
        const float* pp = g_P + ((long)b * LL + (t1 - WIN)) * HH + lane * 4;
        float4 pv[4];
#pragma unroll
        for (int j = 0; j < 4; j++) pv[j] = *(const float4*)(pp + j * 128);
        if (0.0f <= m1) {
            float e = __expf(-m1);
            l1 += cnt * e;
#pragma unroll
            for (int j = 0; j < 4; j++) {
                acc1[j].x += e * pv[j].x; acc1[j].y += e * pv[j].y;
                acc1[j].z += e * pv[j].z; acc1[j].w += e * pv[j].w;
            }
        } else {
            float coef = __expf(m1);
            l1 = l1 * coef + cnt;
#pragma unroll
            for (int j = 0; j < 4; j++) {
                acc1[j].x = acc1[j].x * coef + pv[j].x; acc1[j].y = acc1[j].y * coef + pv[j].y;
                acc1[j].z = acc1[j].z * coef + pv[j].z; acc1[j].w = acc1[j].w * coef + pv[j].w;
            }
            m1 = 0.0f;
        }
    }

    float inv0 = 1.0f / l0, inv1 = 1.0f / l1;
    float* w0 = g_wgt + ((long)b * LL + t0) * HH + lane * 4;
    float* w1 = g_wgt + ((long)b * LL + t1) * HH + lane * 4;
#pragma unroll
    for (int j = 0; j < 4; j++) {
        float4 r0 = make_float4(acc0[j].x * inv0, acc0[j].y * inv0, acc0[j].z * inv0, acc0[j].w * inv0);
        float4 r1 = make_float4(acc1[j].x * inv1, acc1[j].y * inv1, acc1[j].z * inv1, acc1[j].w * inv1);
        *(float4*)(w0 + j * 128) = r0;
        *(float4*)(w1 + j * 128) = r1;
    }
}

// ---------------- launch ----------------
extern "C" void kernel_launch(void* const* d_in, const int* in_sizes, int n_in,
                              void* d_out, int out_size) {
    const float* x        = (const float*)d_in[0];
    const int*   concepts = (const int*)  d_in[1];
    const float* emb      = (const float*)d_in[2];
    const float* Wih      = (const float*)d_in[3];
    const float* Whh      = (const float*)d_in[4];
    const float* bih      = (const float*)d_in[5];
    const float* bhh      = (const float*)d_in[6];
    const float* Wm       = (const float*)d_in[7];
    const float* bm       = (const float*)d_in[8];
    const float* W1       = (const float*)d_in[9];
    const float* b1       = (const float*)d_in[10];
    const float* W2       = (const float*)d_in[11];
    const float* b2       = (const float*)d_in[12];
    float* out = (float*)d_out;

    float *p_pre, *p_cpart, *p_mlp, *p_wgt, *p_h1;
    __nv_bfloat16 *p_xs, *p_wgts, *p_wihs, *p_wms, *p_w1s;
    cudaGetSymbolAddress((void**)&p_pre,   g_pre);
    cudaGetSymbolAddress((void**)&p_cpart, g_cpart);
    cudaGetSymbolAddress((void**)&p_mlp,   g_mlp);
    cudaGetSymbolAddress((void**)&p_wgt,   g_wgt);
    cudaGetSymbolAddress((void**)&p_h1,    g_h1);
    cudaGetSymbolAddress((void**)&p_xs,    g_xs);
    cudaGetSymbolAddress((void**)&p_wgts,  g_wgts);
    cudaGetSymbolAddress((void**)&p_wihs,  g_wihs);
    cudaGetSymbolAddress((void**)&p_wms,   g_wms);
    cudaGetSymbolAddress((void**)&p_w1s,   g_w1s);

    const int lstm_smem = (512 * 16 + 512 * 32 + 16 * 512 + 128) * 4;
    cudaFuncSetAttribute(k_lstm, cudaFuncAttributeMaxDynamicSharedMemorySize, lstm_smem);

    const int M = BB * LL;   // 32768

    k_init<<<128, 256>>>();
    k_cpart<<<BB * 8, 256>>>(emb, concepts, Wih, bih, bhh);

    // bf16 hi|lo splits
    k_split<<<(int)(((long)M * DD) / 1024), 256>>>(x,   DD,     p_xs);
    k_split<<<(G4 * DD) / 1024,             256>>>(Wih, 2 * DD, p_wihs);   // WihA cols 0..511
    k_split<<<(DD * DD) / 1024,             256>>>(Wm,  DD,     p_wms);
    k_split<<<(FF * HH) / 1024,             256>>>(W1,  HH,     p_w1s);

    // pre = x @ WihA^T + cpart (PERMUTED output) -- tensor core mma.sync
    k_mma<0, 1><<<dim3(G4 / 128, M / 128), 256>>>(p_xs, p_wihs, nullptr, p_cpart, p_pre, G4, G4);
    // mlp = x @ Wm^T + bm
    k_mma<0, 0><<<dim3(DD / 128, M / 128), 256>>>(p_xs, p_wms, bm, nullptr, p_mlp, DD, DD);

    // LSTM recurrence
    k_lstm<<<NCTA_LSTM, 256, lstm_smem>>>(p_pre, Whh);

    // blocked prefix sums
    k_csum1<<<dim3(16, BB), 256>>>();
    k_csum2<<<dim3(15, BB), 256>>>();

    // attention
    k_attn<<<2048, 256>>>();

    // h1 = relu(wgt @ W1^T + b1) -- tensor core (split wgt first)
    k_split<<<(int)(((long)M * HH) / 1024), 256>>>(p_wgt, HH, p_wgts);
    k_mma<1, 0><<<dim3(FF / 128, M / 128), 256>>>(p_wgts, p_w1s, b1, nullptr, p_h1, FF, FF);

    // res = h1 @ W2^T + b2 -- scalar (N=100)
    k_gemm<false><<<dim3(1, M / 128), 256>>>(p_h1, FF, W2, FF, b2, out, OUTD, OUTD, FF);
}

// round 11
// speedup vs baseline: 1.6498x; 1.3459x over previous
#include <cuda_runtime.h>
#include <cuda_bf16.h>
#include <math.h>
#include <stdint.h>

// Problem dims
#define BB   32
#define LL   1024
#define DD   512
#define HH   512
#define G4   2048
#define FF   256
#define OUTD 100
#define NCTA_LSTM 128
#define WIN  64          // exact softmax window; beyond this exp(score*decay - m) == exp(-m) in fp32

// ---------------- scratch (device globals; no allocation) ----------------
__device__ float g_pre  [BB * LL * G4];     // gates pre-activation, PERMUTED: [b][t][j*4+gate]
__device__ float g_cpart[BB * G4];          // concept part + biases (original gate order)
__device__ float g_hout [BB * LL * HH];     // LSTM hidden states
__device__ float g_hbuf [4 * 2 * HH * 8];   // per-group h double buffers [group][buf][k][8]
__device__ float g_mlp  [BB * LL * DD];     // mlp_out
__device__ float g_P    [BB * LL * HH];     // cumsum of hout over t
__device__ float g_csum [BB * 16 * HH];     // per-chunk sums for blocked scan
__device__ float g_wgt  [BB * LL * HH];     // attention output
__device__ float g_h1   [BB * LL * FF];     // relu(W1 ...)
__device__ unsigned g_flags[NCTA_LSTM * 32]; // per-CTA step flags, 128B apart

// bf16 hi|lo split operands (stride 1024: cols 0..511 = hi, 512..1023 = lo)
__device__ __nv_bfloat16 g_xs  [BB * LL * 1024];
__device__ __nv_bfloat16 g_wgts[BB * LL * 1024];
__device__ __nv_bfloat16 g_wihs[G4 * 1024];
__device__ __nv_bfloat16 g_wms [DD * 1024];
__device__ __nv_bfloat16 g_w1s [FF * 1024];

// ---------------- PTX helpers ----------------
__device__ __forceinline__ unsigned long long pk2(float lo, float hi) {
    unsigned long long r;
    asm("mov.b64 %0, {%1, %2};" : "=l"(r) : "f"(lo), "f"(hi));
    return r;
}
__device__ __forceinline__ void ffma2(unsigned long long& d, unsigned long long a,
                                      unsigned long long b) {
    asm("fma.rn.f32x2 %0, %1, %2, %0;" : "+l"(d) : "l"(a), "l"(b));
}
__device__ __forceinline__ unsigned ld_acq(const unsigned* p) {
    unsigned v;
    asm volatile("ld.acquire.gpu.global.u32 %0, [%1];" : "=r"(v) : "l"(p));
    return v;
}
__device__ __forceinline__ void st_rel(unsigned* p, unsigned v) {
    asm volatile("st.release.gpu.global.u32 [%0], %1;" :: "l"(p), "r"(v));
}
__device__ __forceinline__ uint32_t s2u(const void* p) {
    uint32_t a;
    asm("{ .reg .u64 t; cvta.to.shared.u64 t, %1; cvt.u32.u64 %0, t; }" : "=r"(a) : "l"(p));
    return a;
}
__device__ __forceinline__ void ldm_x4(uint32_t* r, uint32_t addr) {
    asm volatile("ldmatrix.sync.aligned.m8n8.x4.shared.b16 {%0,%1,%2,%3}, [%4];"
                 : "=r"(r[0]), "=r"(r[1]), "=r"(r[2]), "=r"(r[3]) : "r"(addr));
}
__device__ __forceinline__ void mma16816(float* d, const uint32_t* a, const uint32_t* b) {
    asm volatile("mma.sync.aligned.m16n8k16.row.col.f32.bf16.bf16.f32 "
                 "{%0,%1,%2,%3}, {%4,%5,%6,%7}, {%8,%9}, {%0,%1,%2,%3};"
                 : "+f"(d[0]), "+f"(d[1]), "+f"(d[2]), "+f"(d[3])
                 : "r"(a[0]), "r"(a[1]), "r"(a[2]), "r"(a[3]), "r"(b[0]), "r"(b[1]));
}

// ---------------- init ----------------
__global__ void k_init() {
    int i = blockIdx.x * 256 + threadIdx.x;
    if (i < 4 * 2 * HH * 8) g_hbuf[i] = 0.0f;
    if (i < NCTA_LSTM * 32) g_flags[i] = 0u;
}

// ---------------- fp32 -> bf16 hi|lo split; dst stride 1024, 512-col source block ----
__global__ void k_split(const float* __restrict__ s, int ld, __nv_bfloat16* __restrict__ d) {
    long i = ((long)blockIdx.x * 256 + threadIdx.x) * 4;
    int r = (int)(i >> 9), c = (int)(i & 511);
    float4 v = *(const float4*)(s + (long)r * ld + c);
    float vv[4] = {v.x, v.y, v.z, v.w};
    __nv_bfloat16 h[4], l[4];
#pragma unroll
    for (int j = 0; j < 4; j++) {
        h[j] = __float2bfloat16(vv[j]);
        l[j] = __float2bfloat16(vv[j] - __bfloat162float(h[j]));
    }
    __nv_bfloat16* dh = d + (long)r * 1024 + c;
    *(__nv_bfloat162*)(dh)       = __nv_bfloat162(h[0], h[1]);
    *(__nv_bfloat162*)(dh + 2)   = __nv_bfloat162(h[2], h[3]);
    *(__nv_bfloat162*)(dh + 512) = __nv_bfloat162(l[0], l[1]);
    *(__nv_bfloat162*)(dh + 514) = __nv_bfloat162(l[2], l[3]);
}

// ---------------- cpart[b][g] = emb[concepts[b]] . Wih[g][512:1024] + bih[g] + bhh[g] --------
__global__ void k_cpart(const float* __restrict__ emb, const int* __restrict__ concepts,
                        const float* __restrict__ Wih, const float* __restrict__ bih,
                        const float* __restrict__ bhh) {
    int b = blockIdx.x >> 3;
    int g = ((blockIdx.x & 7) << 8) + threadIdx.x;
    const float4* e = (const float4*)(emb + (long)concepts[b] * HH);
    const float4* w = (const float4*)(Wih + (long)g * (2 * DD) + DD);
    float acc = bih[g] + bhh[g];
#pragma unroll 4
    for (int k = 0; k < HH / 4; k++) {
        float4 wv = __ldg(w + k);
        float4 ev = __ldg(e + k);
        acc += wv.x * ev.x + wv.y * ev.y + wv.z * ev.z + wv.w * ev.w;
    }
    g_cpart[b * G4 + g] = acc;
}

// ---------------- bf16-split tensor-core GEMM (mma.sync m16n8k16) ----------------
template<int RELU, int PERM>
__global__ void __launch_bounds__(256, 2)
k_mma(const __nv_bfloat16* __restrict__ A, const __nv_bfloat16* __restrict__ B,
      const float* __restrict__ bias, const float* __restrict__ rowvec,
      float* __restrict__ C, int ldc, int N) {
    __shared__ __nv_bfloat16 sA[128 * 72];
    __shared__ __nv_bfloat16 sB[128 * 72];
    int tid = threadIdx.x, wid = tid >> 5, lane = tid & 31;
    int wm = (wid >> 2) * 64, wn = (wid & 3) * 32;

    float d[4][4][4];
#pragma unroll
    for (int i = 0; i < 4; i++)
#pragma unroll
        for (int j = 0; j < 4; j++)
#pragma unroll
            for (int q = 0; q < 4; q++) d[i][j][q] = 0.0f;

    uint32_t sAu = s2u(sA), sBu = s2u(sB);
    uint32_t aRow = (uint32_t)(((wm + (lane & 15)) * 72 + (lane >> 4) * 8) * 2);
    uint32_t bRow = (uint32_t)(((wn + (lane >> 4) * 8 + (lane & 7)) * 72 + ((lane >> 3) & 1) * 8) * 2);

    long abase = (long)(blockIdx.y * 128) * 1024;
    long bbase = (long)(blockIdx.x * 128) * 1024;

    for (int kc = 0; kc < 24; kc++) {
        int ao = (kc < 8) ? kc * 64 : (kc < 16) ? 512 + (kc - 8) * 64 : (kc - 16) * 64;
        int bo = (kc < 8) ? kc * 64 : (kc < 16) ? (kc - 8) * 64 : 512 + (kc - 16) * 64;
#pragma unroll
        for (int it = 0; it < 4; it++) {
            int idx = tid + it * 256;
            int r = idx >> 3, cc = (idx & 7) * 8;
            *(uint4*)(sA + r * 72 + cc) = *(const uint4*)(A + abase + (long)r * 1024 + ao + cc);
            *(uint4*)(sB + r * 72 + cc) = *(const uint4*)(B + bbase + (long)r * 1024 + bo + cc);
        }
        __syncthreads();
#pragma unroll
        for (int ks = 0; ks < 4; ks++) {
            uint32_t af[4][4], bq[4], bf[4][2];
#pragma unroll
            for (int mi = 0; mi < 4; mi++)
                ldm_x4(af[mi], sAu + aRow + (uint32_t)((mi * 16 * 72 + ks * 16) * 2));
#pragma unroll
            for (int p = 0; p < 2; p++) {
                ldm_x4(bq, sBu + bRow + (uint32_t)((p * 16 * 72 + ks * 16) * 2));
                bf[p * 2][0]     = bq[0]; bf[p * 2][1]     = bq[1];
                bf[p * 2 + 1][0] = bq[2]; bf[p * 2 + 1][1] = bq[3];
            }
#pragma unroll
            for (int mi = 0; mi < 4; mi++)
#pragma unroll
                for (int nj = 0; nj < 4; nj++)
                    mma16816(d[mi][nj], af[mi], bf[nj]);
        }
        __syncthreads();
    }

    int g = lane >> 2, t2 = (lane & 3) * 2;
#pragma unroll
    for (int mi = 0; mi < 4; mi++) {
#pragma unroll
        for (int half = 0; half < 2; half++) {
            int mg = blockIdx.y * 128 + wm + mi * 16 + g + half * 8;
            const float* rv = rowvec ? (rowvec + (long)(mg >> 10) * N) : nullptr;
            float* crow = C + (long)mg * ldc;
#pragma unroll
            for (int nj = 0; nj < 4; nj++) {
                int n = blockIdx.x * 128 + wn + nj * 8 + t2;
                float v0 = d[mi][nj][half * 2];
                float v1 = d[mi][nj][half * 2 + 1];
                if (bias) { v0 += bias[n]; v1 += bias[n + 1]; }
                if (rv)   { v0 += rv[n];   v1 += rv[n + 1]; }
                if (RELU) { v0 = fmaxf(v0, 0.0f); v1 = fmaxf(v1, 0.0f); }
                if (PERM) {
                    crow[(((n)     & 511) << 2) | ((n)     >> 9)] = v0;
                    crow[(((n + 1) & 511) << 2) | ((n + 1) >> 9)] = v1;
                } else {
                    *(float2*)(crow + n) = make_float2(v0, v1);
                }
            }
        }
    }
}

// ---------------- scalar SGEMM (FF2 only: N=100, K=256) ----------------
template<bool RELU>
__global__ void k_gemm(const float* __restrict__ A, int lda,
                       const float* __restrict__ W, int ldw,
                       const float* __restrict__ bias,
                       float* __restrict__ C, int ldc,
                       int N, int K) {
    __shared__ float As[16 * 132];
    __shared__ float Bs[16 * 132];
    int tid = threadIdx.x;
    int bx = blockIdx.x, by = blockIdx.y;
    int tx = tid & 15, ty = tid >> 4;

    float acc[8][8];
#pragma unroll
    for (int i = 0; i < 8; i++)
#pragma unroll
        for (int j = 0; j < 8; j++) acc[i][j] = 0.0f;

    int row = tid >> 2;
    int kl  = (tid & 3) * 4;
    const float* Abase = A + (long)(by * 128 + row) * lda + kl;
    int n0l = bx * 128 + row, n1l = n0l + 64;
    const float* W0 = (n0l < N) ? (W + (long)n0l * ldw + kl) : nullptr;
    const float* W1 = (n1l < N) ? (W + (long)n1l * ldw + kl) : nullptr;

    for (int kt = 0; kt < K; kt += 16) {
        float4 a0 = *(const float4*)(Abase + kt);
        float4 a1 = *(const float4*)(Abase + kt + (long)64 * lda);
        float4 b0 = make_float4(0.f, 0.f, 0.f, 0.f);
        float4 b1 = make_float4(0.f, 0.f, 0.f, 0.f);
        if (W0) b0 = *(const float4*)(W0 + kt);
        if (W1) b1 = *(const float4*)(W1 + kt);
#pragma unroll
        for (int q = 0; q < 4; q++) {
            float av0 = q == 0 ? a0.x : q == 1 ? a0.y : q == 2 ? a0.z : a0.w;
            float av1 = q == 0 ? a1.x : q == 1 ? a1.y : q == 2 ? a1.z : a1.w;
            float bv0 = q == 0 ? b0.x : q == 1 ? b0.y : q == 2 ? b0.z : b0.w;
            float bv1 = q == 0 ? b1.x : q == 1 ? b1.y : q == 2 ? b1.z : b1.w;
            As[(kl + q) * 132 + row]      = av0;
            As[(kl + q) * 132 + row + 64] = av1;
            Bs[(kl + q) * 132 + row]      = bv0;
            Bs[(kl + q) * 132 + row + 64] = bv1;
        }
        __syncthreads();
#pragma unroll
        for (int k = 0; k < 16; k++) {
            float4 av0 = *(const float4*)&As[k * 132 + ty * 8];
            float4 av1 = *(const float4*)&As[k * 132 + ty * 8 + 4];
            float4 bv0 = *(const float4*)&Bs[k * 132 + tx * 8];
            float4 bv1 = *(const float4*)&Bs[k * 132 + tx * 8 + 4];
            float a[8] = {av0.x, av0.y, av0.z, av0.w, av1.x, av1.y, av1.z, av1.w};
            float b[8] = {bv0.x, bv0.y, bv0.z, bv0.w, bv1.x, bv1.y, bv1.z, bv1.w};
#pragma unroll
            for (int i = 0; i < 8; i++)
#pragma unroll
                for (int j = 0; j < 8; j++) acc[i][j] += a[i] * b[j];
        }
        __syncthreads();
    }

    int m0 = by * 128 + ty * 8, nn0 = bx * 128 + tx * 8;
#pragma unroll
    for (int i = 0; i < 8; i++) {
        int m = m0 + i;
#pragma unroll
        for (int j = 0; j < 8; j++) {
            int n = nn0 + j;
            if (n < N) {
                float v = acc[i][j];
                if (bias) v += bias[n];
                if (RELU) v = fmaxf(v, 0.0f);
                C[(long)m * ldc + n] = v;
            }
        }
    }
}

// ---------------- persistent LSTM: 4 independent batch-groups x 32 CTAs ----------------
// group = blockIdx.x>>5 owns batches [group*8, group*8+8); gcta = blockIdx.x&31 owns
// hidden dims [gcta*16, gcta*16+16) => 64 gate rows (Whh slice 128KB in smem).
// 16 k-slices of width 32 (half-warp each); thread tile 8 rows x 4 batches (16 f32x2).
// Warp w stages h rows k in [64w,64w+64) (1KB) and polls only its 4 producer flags.
// Groups are fully independent: no cross-group synchronization.
__global__ void __launch_bounds__(256, 1)
k_lstm(const float* __restrict__ pre, const float* __restrict__ Whh) {
    extern __shared__ float sm[];
    float* w_t = sm;                    // [512][64]  k-major weights (64 gate rows)
    float* h_s = w_t + 512 * 64;        // [512][8]   staged h for this group
    float* ps  = h_s + 512 * 8;         // [16][512]  swizzled k-split partials
    float* c_s = ps + 16 * 512;         // [128]      cell state

    int tid   = threadIdx.x;
    int group = blockIdx.x >> 5;
    int gcta  = blockIdx.x & 31;
    int j0    = gcta * 16;
    int b0    = group * 8;
    int w     = tid >> 5;
    int lane  = tid & 31;

    // load Whh slice k-major: w_t[k*64 + lr] = Whh[grow(lr)][k], grow = (lr>>4)*512 + j0 + (lr&15)
    for (int i = tid; i < 64 * 512; i += 256) {
        int lr = i & 63, k = i >> 6;
        int grow = ((lr >> 4) << 9) + j0 + (lr & 15);
        w_t[k * 64 + lr] = Whh[(long)grow * HH + k];
    }
    if (tid < 128) c_s[tid] = 0.0f;

    // compute roles: 16 slices x 16 threads; tile 8 rows x 4 batches
    int ks  = tid >> 4;
    int l16 = tid & 15;
    int rt  = l16 >> 1;       // rows rt*8..+8
    int bt  = l16 & 1;        // batches bt*4..+4
    const float* wbase = w_t + (ks * 32) * 64 + rt * 8;
    const float* hbase = h_s + (ks * 32) * 8 + bt * 4;
    float* psbase = ps + ks * 512 + l16 * 32;

    // act roles (tid < 128): hidden jl = tid>>3 (0..15), batch ab = tid&7
    int jl = tid >> 3, ab = tid & 7;
    long preoff = (long)(b0 + ab) * LL * G4 + (j0 + jl) * 4;
    int slot_r = ((jl >> 1) & 3) ^ ((ab >> 2) << 1);
    int gb[4];
#pragma unroll
    for (int g = 0; g < 4; g++)
        gb[g] = g * 128 + ((jl >> 3) << 6) + ((ab >> 2) << 5) + slot_r * 8
              + ((ab & 3) << 1) + (jl & 1);

    float* hb_base = g_hbuf + group * 8192;         // 2 bufs x 512 x 8
    unsigned* myflag = &g_flags[blockIdx.x * 32];
    const unsigned* pollflag = &g_flags[(group * 32 + w * 4 + (lane & 3)) * 32];

    __syncthreads();

    float4 pf4 = make_float4(0.f, 0.f, 0.f, 0.f);
    if (tid < 128) pf4 = *(const float4*)(pre + preoff);    // t = 0

    for (int t = 0; t < LL; t++) {
        // ---- per-warp: wait for this warp's 4 producers, stage 1KB of h ----
        while (ld_acq(pollflag) < (unsigned)t) { }
        __syncwarp();
        {
            const float4* hin = (const float4*)(hb_base + (t & 1) * 4096) + w * 128;
            float4* hdst = (float4*)h_s + w * 128;
#pragma unroll
            for (int i = 0; i < 4; i++)
                hdst[lane + 32 * i] = __ldcg(hin + lane + 32 * i);
        }
        __syncwarp();

        // ---- compute: 16 f32x2 accumulators over own 32-wide k-slice ----
        unsigned long long acc[4][4];
#pragma unroll
        for (int rp = 0; rp < 4; rp++)
#pragma unroll
            for (int j = 0; j < 4; j++) acc[rp][j] = 0ull;

#pragma unroll 4
        for (int k = 0; k < 32; k++) {
            float4 wv0 = *(const float4*)(wbase + k * 64);
            float4 wv1 = *(const float4*)(wbase + k * 64 + 4);
            float4 hv  = *(const float4*)(hbase + k * 8);
            unsigned long long wp0 = pk2(wv0.x, wv0.y);
            unsigned long long wp1 = pk2(wv0.z, wv0.w);
            unsigned long long wp2 = pk2(wv1.x, wv1.y);
            unsigned long long wp3 = pk2(wv1.z, wv1.w);
            unsigned long long h0 = pk2(hv.x, hv.x);
            unsigned long long h1 = pk2(hv.y, hv.y);
            unsigned long long h2 = pk2(hv.z, hv.z);
            unsigned long long h3 = pk2(hv.w, hv.w);
            ffma2(acc[0][0], wp0, h0); ffma2(acc[0][1], wp0, h1);
            ffma2(acc[0][2], wp0, h2); ffma2(acc[0][3], wp0, h3);
            ffma2(acc[1][0], wp1, h0); ffma2(acc[1][1], wp1, h1);
            ffma2(acc[1][2], wp1, h2); ffma2(acc[1][3], wp1, h3);
            ffma2(acc[2][0], wp2, h0); ffma2(acc[2][1], wp2, h1);
            ffma2(acc[2][2], wp2, h2); ffma2(acc[2][3], wp2, h3);
            ffma2(acc[3][0], wp3, h0); ffma2(acc[3][1], wp3, h1);
            ffma2(acc[3][2], wp3, h2); ffma2(acc[3][3], wp3, h3);
        }
        // swizzled partial store: slot = rp ^ (bt<<1); floats [slot*8 + j*2 + hilo]
#pragma unroll
        for (int rp = 0; rp < 4; rp++) {
            int slot = rp ^ (bt << 1);
            *(ulonglong2*)(psbase + slot * 8)     = make_ulonglong2(acc[rp][0], acc[rp][1]);
            *(ulonglong2*)(psbase + slot * 8 + 4) = make_ulonglong2(acc[rp][2], acc[rp][3]);
        }
        __syncthreads();

        // ---- fused reduce + activation + publish (tid < 128) ----
        if (tid < 128) {
            float gs0 = 0.f, gs1 = 0.f, gs2 = 0.f, gs3 = 0.f;
#pragma unroll
            for (int kk = 0; kk < 16; kk++) {
                const float* pk = ps + kk * 512;
                gs0 += pk[gb[0]];
                gs1 += pk[gb[1]];
                gs2 += pk[gb[2]];
                gs3 += pk[gb[3]];
            }
            float gi = gs0 + pf4.x;
            float gf = gs1 + pf4.y;
            float gg = gs2 + pf4.z;
            float go = gs3 + pf4.w;
            float si = __fdividef(1.0f, 1.0f + __expf(-gi));
            float sf = __fdividef(1.0f, 1.0f + __expf(-gf));
            float so = __fdividef(1.0f, 1.0f + __expf(-go));
            float ag = fabsf(gg);
            float eg = __expf(-2.0f * ag);
            float tg = copysignf(__fdividef(1.0f - eg, 1.0f + eg), gg);
            float c  = sf * c_s[tid] + si * tg;
            c_s[tid] = c;
            float ac = fabsf(c);
            float ec = __expf(-2.0f * ac);
            float tc = copysignf(__fdividef(1.0f - ec, 1.0f + ec), c);
            float h  = so * tc;
            hb_base[((t + 1) & 1) * 4096 + (j0 + jl) * 8 + ab] = h;
            g_hout[((long)(b0 + ab) * LL + t) * HH + j0 + jl] = h;
            if (t + 1 < LL)
                pf4 = *(const float4*)(pre + preoff + (long)(t + 1) * G4);
        }
        __syncthreads();
        if (tid == 0) st_rel(myflag, (unsigned)(t + 1));
    }
}

// ---------------- blocked cumsum ----------------
__global__ void k_csum1() {
    int c = blockIdx.x, b = blockIdx.y;
    int d = threadIdx.x;
    const float* s0 = g_hout + ((long)b * LL + c * 64) * HH + d;
    const float* s1 = s0 + 256;
    float* d0 = g_P + ((long)b * LL + c * 64) * HH + d;
    float* d1 = d0 + 256;
    float a0 = 0.f, a1 = 0.f;
#pragma unroll 8
    for (int t = 0; t < 64; t++) {
        a0 += s0[t * HH]; d0[t * HH] = a0;
        a1 += s1[t * HH]; d1[t * HH] = a1;
    }
    g_csum[((long)b * 16 + c) * HH + d]       = a0;
    g_csum[((long)b * 16 + c) * HH + d + 256] = a1;
}

__global__ void k_csum2() {
    int c = blockIdx.x + 1, b = blockIdx.y;
    int d = threadIdx.x;
    float o0 = 0.f, o1 = 0.f;
    for (int cc = 0; cc < c; cc++) {
        o0 += g_csum[((long)b * 16 + cc) * HH + d];
        o1 += g_csum[((long)b * 16 + cc) * HH + d + 256];
    }
    float* d0 = g_P + ((long)b * LL + c * 64) * HH + d;
    float* d1 = d0 + 256;
#pragma unroll 8
    for (int t = 0; t < 64; t++) {
        d0[t * HH] += o0;
        d1[t * HH] += o1;
    }
}

// ---------------- banded online-softmax attention ----------------
__device__ __forceinline__ void upd(float& m, float& l, float4* acc, float sc, const float4* ov) {
    if (sc <= m) {
        float e = __expf(sc - m);
        l += e;
#pragma unroll
        for (int j = 0; j < 4; j++) {
            acc[j].x += e * ov[j].x; acc[j].y += e * ov[j].y;
            acc[j].z += e * ov[j].z; acc[j].w += e * ov[j].w;
        }
    } else {
        float coef = __expf(m - sc);
        l = l * coef + 1.0f;
#pragma unroll
        for (int j = 0; j < 4; j++) {
            acc[j].x = acc[j].x * coef + ov[j].x; acc[j].y = acc[j].y * coef + ov[j].y;
            acc[j].z = acc[j].z * coef + ov[j].z; acc[j].w = acc[j].w * coef + ov[j].w;
        }
        m = sc;
    }
}

__global__ void k_attn() {
    int warp = (blockIdx.x * blockDim.x + threadIdx.x) >> 5;
    int lane = threadIdx.x & 31;
    int b  = warp >> 9;
    int tp = warp & 511;
    int t0 = tp * 2, t1 = t0 + 1;

    const float* mb = g_mlp  + (long)b * LL * DD;
    const float* ob = g_hout + (long)b * LL * HH;

    float4 q0[4], q1[4], acc0[4], acc1[4];
#pragma unroll
    for (int j = 0; j < 4; j++) {
        q0[j] = *(const float4*)(mb + (long)t0 * DD + lane * 4 + j * 128);
        q1[j] = *(const float4*)(mb + (long)t1 * DD + lane * 4 + j * 128);
        acc0[j] = make_float4(0.f, 0.f, 0.f, 0.f);
        acc1[j] = make_float4(0.f, 0.f, 0.f, 0.f);
    }
    float m0 = -1e30f, m1 = -1e30f, l0 = 0.0f, l1 = 0.0f;

    int slo = t0 - (WIN - 1); if (slo < 0) slo = 0;
    for (int s = slo; s <= t1; s++) {
        float4 ov[4];
        const float* op = ob + (long)s * HH + lane * 4;
#pragma unroll
        for (int j = 0; j < 4; j++) ov[j] = *(const float4*)(op + j * 128);
        float d0 = 0.f, d1 = 0.f;
#pragma unroll
        for (int j = 0; j < 4; j++) {
            d0 += q0[j].x * ov[j].x + q0[j].y * ov[j].y + q0[j].z * ov[j].z + q0[j].w * ov[j].w;
            d1 += q1[j].x * ov[j].x + q1[j].y * ov[j].y + q1[j].z * ov[j].z + q1[j].w * ov[j].w;
        }
#pragma unroll
        for (int off = 16; off; off >>= 1) {
            d0 += __shfl_xor_sync(0xFFFFFFFFu, d0, off);
            d1 += __shfl_xor_sync(0xFFFFFFFFu, d1, off);
        }
        if (s <= t0) {
            float sc = d0 * __expf(-0.6f * (float)(t0 - s));
            upd(m0, l0, acc0, sc, ov);
        }
        if (s >= t1 - (WIN - 1)) {
            float sc = d1 * __expf(-0.6f * (float)(t1 - s));
            upd(m1, l1, acc1, sc, ov);
        }
    }
    if (t0 >= WIN) {
        float cnt = (float)(t0 - (WIN - 1));
        const float* pp = g_P + ((long)b * LL + (t0 - WIN)) * HH + lane * 4;
        float4 pv[4];
#pragma unroll
        for (int j = 0; j < 4; j++) pv[j] = *(const float4*)(pp + j * 128);
        if (0.0f <= m0) {
            float e = __expf(-m0);
            l0 += cnt * e;
#pragma unroll
            for (int j = 0; j < 4; j++) {
                acc0[j].x += e * pv[j].x; acc0[j].y += e * pv[j].y;
                acc0[j].z += e * pv[j].z; acc0[j].w += e * pv[j].w;
            }
        } else {
            float coef = __expf(m0);
            l0 = l0 * coef + cnt;
#pragma unroll
            for (int j = 0; j < 4; j++) {
                acc0[j].x = acc0[j].x * coef + pv[j].x; acc0[j].y = acc0[j].y * coef + pv[j].y;
                acc0[j].z = acc0[j].z * coef + pv[j].z; acc0[j].w = acc0[j].w * coef + pv[j].w;
            }
            m0 = 0.0f;
        }
    }
    if (t1 >= WIN) {
        float cnt = (float)(t1 - (WIN - 1));
        const float* pp = g_P + ((long)b * LL + (t1 - WIN)) * HH + lane * 4;
        float4 pv[4];
#pragma unroll
        for (int j = 0; j < 4; j++) pv[j] = *(const float4*)(pp + j * 128);
        if (0.0f <= m1) {
            float e = __expf(-m1);
            l1 += cnt * e;
#pragma unroll
            for (int j = 0; j < 4; j++) {
                acc1[j].x += e * pv[j].x; acc1[j].y += e * pv[j].y;
                acc1[j].z += e * pv[j].z; acc1[j].w += e * pv[j].w;
            }
        } else {
            float coef = __expf(m1);
            l1 = l1 * coef + cnt;
#pragma unroll
            for (int j = 0; j < 4; j++) {
                acc1[j].x = acc1[j].x * coef + pv[j].x; acc1[j].y = acc1[j].y * coef + pv[j].y;
                acc1[j].z = acc1[j].z * coef + pv[j].z; acc1[j].w = acc1[j].w * coef + pv[j].w;
            }
            m1 = 0.0f;
        }
    }

    float inv0 = 1.0f / l0, inv1 = 1.0f / l1;
    float* w0 = g_wgt + ((long)b * LL + t0) * HH + lane * 4;
    float* w1 = g_wgt + ((long)b * LL + t1) * HH + lane * 4;
#pragma unroll
    for (int j = 0; j < 4; j++) {
        float4 r0 = make_float4(acc0[j].x * inv0, acc0[j].y * inv0, acc0[j].z * inv0, acc0[j].w * inv0);
        float4 r1 = make_float4(acc1[j].x * inv1, acc1[j].y * inv1, acc1[j].z * inv1, acc1[j].w * inv1);
        *(float4*)(w0 + j * 128) = r0;
        *(float4*)(w1 + j * 128) = r1;
    }
}

// ---------------- launch ----------------
extern "C" void kernel_launch(void* const* d_in, const int* in_sizes, int n_in,
                              void* d_out, int out_size) {
    const float* x        = (const float*)d_in[0];
    const int*   concepts = (const int*)  d_in[1];
    const float* emb      = (const float*)d_in[2];
    const float* Wih      = (const float*)d_in[3];
    const float* Whh      = (const float*)d_in[4];
    const float* bih      = (const float*)d_in[5];
    const float* bhh      = (const float*)d_in[6];
    const float* Wm       = (const float*)d_in[7];
    const float* bm       = (const float*)d_in[8];
    const float* W1       = (const float*)d_in[9];
    const float* b1       = (const float*)d_in[10];
    const float* W2       = (const float*)d_in[11];
    const float* b2       = (const float*)d_in[12];
    float* out = (float*)d_out;

    float *p_pre, *p_cpart, *p_mlp, *p_wgt, *p_h1;
    __nv_bfloat16 *p_xs, *p_wgts, *p_wihs, *p_wms, *p_w1s;
    cudaGetSymbolAddress((void**)&p_pre,   g_pre);
    cudaGetSymbolAddress((void**)&p_cpart, g_cpart);
    cudaGetSymbolAddress((void**)&p_mlp,   g_mlp);
    cudaGetSymbolAddress((void**)&p_wgt,   g_wgt);
    cudaGetSymbolAddress((void**)&p_h1,    g_h1);
    cudaGetSymbolAddress((void**)&p_xs,    g_xs);
    cudaGetSymbolAddress((void**)&p_wgts,  g_wgts);
    cudaGetSymbolAddress((void**)&p_wihs,  g_wihs);
    cudaGetSymbolAddress((void**)&p_wms,   g_wms);
    cudaGetSymbolAddress((void**)&p_w1s,   g_w1s);

    // smem: w_t 128KB + h_s 16KB + ps 32KB + c_s 512B = ~176.5KB
    const int lstm_smem = (512 * 64 + 512 * 8 + 16 * 512 + 128) * 4;
    cudaFuncSetAttribute(k_lstm, cudaFuncAttributeMaxDynamicSharedMemorySize, lstm_smem);

    const int M = BB * LL;   // 32768

    k_init<<<128, 256>>>();
    k_cpart<<<BB * 8, 256>>>(emb, concepts, Wih, bih, bhh);

    // bf16 hi|lo splits
    k_split<<<(int)(((long)M * DD) / 1024), 256>>>(x,   DD,     p_xs);
    k_split<<<(G4 * DD) / 1024,             256>>>(Wih, 2 * DD, p_wihs);   // WihA cols 0..511
    k_split<<<(DD * DD) / 1024,             256>>>(Wm,  DD,     p_wms);
    k_split<<<(FF * HH) / 1024,             256>>>(W1,  HH,     p_w1s);

    // pre = x @ WihA^T + cpart (PERMUTED output) -- tensor core mma.sync
    k_mma<0, 1><<<dim3(G4 / 128, M / 128), 256>>>(p_xs, p_wihs, nullptr, p_cpart, p_pre, G4, G4);
    // mlp = x @ Wm^T + bm
    k_mma<0, 0><<<dim3(DD / 128, M / 128), 256>>>(p_xs, p_wms, bm, nullptr, p_mlp, DD, DD);

    // LSTM recurrence (4 independent batch-groups x 32 CTAs)
    k_lstm<<<NCTA_LSTM, 256, lstm_smem>>>(p_pre, Whh);

    // blocked prefix sums
    k_csum1<<<dim3(16, BB), 256>>>();
    k_csum2<<<dim3(15, BB), 256>>>();

    // attention
    k_attn<<<2048, 256>>>();

    // h1 = relu(wgt @ W1^T + b1) -- tensor core (split wgt first)
    k_split<<<(int)(((long)M * HH) / 1024), 256>>>(p_wgt, HH, p_wgts);
    k_mma<1, 0><<<dim3(FF / 128, M / 128), 256>>>(p_wgts, p_w1s, b1, nullptr, p_h1, FF, FF);

    // res = h1 @ W2^T + b2 -- scalar (N=100)
    k_gemm<false><<<dim3(1, M / 128), 256>>>(p_h1, FF, W2, FF, b2, out, OUTD, OUTD, FF);
}